// round 16
// baseline (speedup 1.0000x reference)
#include <cuda_runtime.h>
#include <cuda_fp16.h>
#include <stdint.h>

// SelfAttentionEasy b=2,h=16,s=2048,d=64 fp32
// out = (exp(Q@K/8) @ V) / rowsum(exp(Q@K/8))
// Round 15: R8 config (BM=64, 4 warps, 4 CTAs/SM = 16 warps/SM) with the
// exp->PV seam cleared: rowsum deferred after PV, V(jp=0) frags prefetched
// under the ex2 chain. Otherwise byte-identical to R8.

#define S_LEN 2048
#define D     64
#define BM    64
#define BN    64
#define NELEM (2*16*64*2048)          // elements per tensor (k or v)
#define QSCALE 0.18033688011112042f   // log2(e)/8

__device__ __half g_kh[NELEM];        // k as fp16, layout [bh][d][s]
__device__ __half g_vh[NELEM];        // v as fp16, layout [bh][s][d]

#define SM_TOTAL 49152                // 3 stages x (8KB K + 8KB V)

#define SWZ(o) ((uint32_t)(o) ^ ((((uint32_t)(o)) >> 3) & 0x70))

__device__ __forceinline__ uint32_t smem_u32(const void* p) {
    uint32_t a;
    asm("{ .reg .u64 t; cvta.to.shared.u64 t, %1; cvt.u32.u64 %0, t; }"
        : "=r"(a) : "l"(p));
    return a;
}
__device__ __forceinline__ uint32_t h2u(__half2 h) {
    return *reinterpret_cast<uint32_t*>(&h);
}

#define LDSM4(r, a) asm volatile(                                          \
    "ldmatrix.sync.aligned.m8n8.x4.shared.b16 {%0,%1,%2,%3}, [%4];"        \
    : "=r"((r)[0]),"=r"((r)[1]),"=r"((r)[2]),"=r"((r)[3]) : "r"(a))

#define LDSM4T(r, a) asm volatile(                                         \
    "ldmatrix.sync.aligned.m8n8.x4.trans.shared.b16 {%0,%1,%2,%3}, [%4];"  \
    : "=r"((r)[0]),"=r"((r)[1]),"=r"((r)[2]),"=r"((r)[3]) : "r"(a))

#define MMA(c, a, b0, b1) asm volatile(                                    \
    "mma.sync.aligned.m16n8k16.row.col.f32.f16.f16.f32 "                   \
    "{%0,%1,%2,%3},{%4,%5,%6,%7},{%8,%9},{%0,%1,%2,%3};"                   \
    : "+f"((c)[0]),"+f"((c)[1]),"+f"((c)[2]),"+f"((c)[3])                  \
    : "r"((a)[0]),"r"((a)[1]),"r"((a)[2]),"r"((a)[3]),"r"(b0),"r"(b1))

#define CPA(dst, src) asm volatile(                                        \
    "cp.async.cg.shared.global [%0], [%1], 16;" :: "r"(dst), "l"(src))
#define CPA_COMMIT() asm volatile("cp.async.commit_group;" ::: "memory")
#define CPA_WAIT1()  asm volatile("cp.async.wait_group 1;" ::: "memory")
#define CPA_WAIT0()  asm volatile("cp.async.wait_group 0;" ::: "memory")

// ---- fused prepass: fp32 -> fp16 bulk convert for K and V ----
__global__ void cvt_kv(const float* __restrict__ k, const float* __restrict__ v) {
    size_t gi = (size_t)blockIdx.x * blockDim.x + threadIdx.x;
    const size_t half = (size_t)NELEM / 8;
    const float* src;
    __half* dst;
    size_t i;
    if (gi < half) { src = k; dst = g_kh; i = gi * 8; }
    else           { src = v; dst = g_vh; i = (gi - half) * 8; }
    float4 a = *reinterpret_cast<const float4*>(src + i);
    float4 b = *reinterpret_cast<const float4*>(src + i + 4);
    uint4 o;
    o.x = h2u(__floats2half2_rn(a.x, a.y));
    o.y = h2u(__floats2half2_rn(a.z, a.w));
    o.z = h2u(__floats2half2_rn(b.x, b.y));
    o.w = h2u(__floats2half2_rn(b.z, b.w));
    *reinterpret_cast<uint4*>(dst + i) = o;
}

__global__ __launch_bounds__(128, 4)
void attn_hmma(const float* __restrict__ q, float* __restrict__ out)
{
    extern __shared__ char smem[];
    const uint32_t sb = smem_u32(smem);
    const int tid = threadIdx.x;
    const int wid = tid >> 5, lane = tid & 31;
    const int bh = blockIdx.y;
    const int q0 = blockIdx.x * BM;

    const float*  qb  = q + (size_t)bh * S_LEN * D + (size_t)q0 * D;
    const __half* khb = g_kh + (size_t)bh * D * S_LEN;
    const __half* vhb = g_vh + (size_t)bh * S_LEN * D;
    float*        ob  = out + (size_t)bh * S_LEN * D + (size_t)q0 * D;

    const int wrow = wid * 16;
    const uint32_t arow = (uint32_t)(wrow + (lane & 15));
    const uint32_t acb  = (uint32_t)(lane & 16);
    const uint32_t brow = (uint32_t)(lane & 15);
    const uint32_t bcb  = (uint32_t)(lane & 16);

    // ---- stage Q once (pre-scaled by log2e/8), hoist frags to regs ----
    #pragma unroll
    for (int i = 0; i < 8; i++) {
        int s = tid + i * 128;                 // 1024 float4 slots
        int row = s >> 4, c4 = s & 15;
        float4 f = *reinterpret_cast<const float4*>(qb + row * D + c4 * 4);
        uint32_t off = SWZ(row * 128 + c4 * 8);
        *reinterpret_cast<uint2*>(smem + off) =
            make_uint2(h2u(__floats2half2_rn(f.x * QSCALE, f.y * QSCALE)),
                       h2u(__floats2half2_rn(f.z * QSCALE, f.w * QSCALE)));
    }
    __syncthreads();
    uint32_t aq[4][4];
    #pragma unroll
    for (int kk = 0; kk < 4; kk++)
        LDSM4(aq[kk], sb + SWZ(arow * 128 + 32 * kk + acb));
    __syncthreads();   // Q frags read; smem reusable

    // per-thread cp.async source rows/chunks (512 K-chunks + 512 V-chunks)
    const int r0_ = (tid      ) >> 3, c0_ = (tid      ) & 7;
    const int r1_ = (tid + 128) >> 3, c1_ = (tid + 128) & 7;
    const int r2_ = (tid + 256) >> 3, c2_ = (tid + 256) & 7;
    const int r3_ = (tid + 384) >> 3, c3_ = (tid + 384) & 7;

    // ---- cp.async prologue: stages for tiles 0 and 1 ----
    #pragma unroll
    for (int p = 0; p < 2; p++) {
        uint32_t kd = sb + p * 16384;
        uint32_t vd = kd + 8192;
        const int t0 = p * BN;
        CPA(kd + SWZ(r0_ * 128 + c0_ * 16), khb + (size_t)r0_ * S_LEN + t0 + c0_ * 8);
        CPA(kd + SWZ(r1_ * 128 + c1_ * 16), khb + (size_t)r1_ * S_LEN + t0 + c1_ * 8);
        CPA(kd + SWZ(r2_ * 128 + c2_ * 16), khb + (size_t)r2_ * S_LEN + t0 + c2_ * 8);
        CPA(kd + SWZ(r3_ * 128 + c3_ * 16), khb + (size_t)r3_ * S_LEN + t0 + c3_ * 8);
        CPA(vd + SWZ(r0_ * 128 + c0_ * 16), vhb + (size_t)(t0 + r0_) * D + c0_ * 8);
        CPA(vd + SWZ(r1_ * 128 + c1_ * 16), vhb + (size_t)(t0 + r1_) * D + c1_ * 8);
        CPA(vd + SWZ(r2_ * 128 + c2_ * 16), vhb + (size_t)(t0 + r2_) * D + c2_ * 8);
        CPA(vd + SWZ(r3_ * 128 + c3_ * 16), vhb + (size_t)(t0 + r3_) * D + c3_ * 8);
        CPA_COMMIT();
    }

    float O[8][4];
    #pragma unroll
    for (int j = 0; j < 8; j++)
        #pragma unroll
        for (int e = 0; e < 4; e++) O[j][e] = 0.f;
    float lsum0 = 0.f, lsum1 = 0.f;

    int scur = 0, snxt = 2;

    for (int t = 0; t < 32; t++) {
        if (t < 31) { CPA_WAIT1(); } else { CPA_WAIT0(); }
        __syncthreads();

        // issue tile t+2 into stage snxt
        if (t + 2 < 32) {
            uint32_t kd = sb + snxt * 16384;
            uint32_t vd = kd + 8192;
            const int t0 = (t + 2) * BN;
            CPA(kd + SWZ(r0_ * 128 + c0_ * 16), khb + (size_t)r0_ * S_LEN + t0 + c0_ * 8);
            CPA(kd + SWZ(r1_ * 128 + c1_ * 16), khb + (size_t)r1_ * S_LEN + t0 + c1_ * 8);
            CPA(kd + SWZ(r2_ * 128 + c2_ * 16), khb + (size_t)r2_ * S_LEN + t0 + c2_ * 8);
            CPA(kd + SWZ(r3_ * 128 + c3_ * 16), khb + (size_t)r3_ * S_LEN + t0 + c3_ * 8);
            CPA(vd + SWZ(r0_ * 128 + c0_ * 16), vhb + (size_t)(t0 + r0_) * D + c0_ * 8);
            CPA(vd + SWZ(r1_ * 128 + c1_ * 16), vhb + (size_t)(t0 + r1_) * D + c1_ * 8);
            CPA(vd + SWZ(r2_ * 128 + c2_ * 16), vhb + (size_t)(t0 + r2_) * D + c2_ * 8);
            CPA(vd + SWZ(r3_ * 128 + c3_ * 16), vhb + (size_t)(t0 + r3_) * D + c3_ * 8);
            CPA_COMMIT();
        }

        const uint32_t Kb = sb + scur * 16384;
        const uint32_t Vb = Kb + 8192;

        // ---- S = (Q*log2e/8) @ K^T (8 independent chains) ----
        float S[8][4];
        #pragma unroll
        for (int j = 0; j < 8; j++)
            #pragma unroll
            for (int e = 0; e < 4; e++) S[j][e] = 0.f;

        #pragma unroll
        for (int kk = 0; kk < 4; kk++) {
            #pragma unroll
            for (int jp = 0; jp < 4; jp++) {
                uint32_t b[4];
                LDSM4T(b, Kb + SWZ((16 * kk + brow) * 128 + 32 * jp + bcb));
                MMA(S[2*jp],   aq[kk], b[0], b[1]);
                MMA(S[2*jp+1], aq[kk], b[2], b[3]);
            }
        }

        // ---- prefetch V(jp=0) frags: LDS latency hides under ex2 chain ----
        uint32_t vb0[4], vb1[4];
        LDSM4T(vb0, Vb + SWZ((      brow) * 128 +  0 + bcb));
        LDSM4T(vb1, Vb + SWZ((      brow) * 128 + 32 + bcb));

        // ---- p = ex2(S) fp16x2 -> PV A-frags (rowsum deferred) ----
        uint32_t aph[4][4];
        #pragma unroll
        for (int j = 0; j < 8; j++) {
            uint32_t u0 = h2u(__floats2half2_rn(S[j][0], S[j][1]));
            uint32_t u1 = h2u(__floats2half2_rn(S[j][2], S[j][3]));
            asm("ex2.approx.f16x2 %0, %0;" : "+r"(u0));
            asm("ex2.approx.f16x2 %0, %0;" : "+r"(u1));
            int kk = j >> 1, pc = (j & 1) * 2;
            aph[kk][pc]   = u0;
            aph[kk][pc+1] = u1;
        }

        // ---- O += P @ V (jp=0 uses prefetched frags) ----
        MMA(O[0], aph[0], vb0[0], vb0[1]);
        MMA(O[1], aph[0], vb0[2], vb0[3]);
        MMA(O[2], aph[0], vb1[0], vb1[1]);
        MMA(O[3], aph[0], vb1[2], vb1[3]);
        {
            uint32_t b[4];
            LDSM4T(b, Vb + SWZ((brow) * 128 + 64 + bcb));
            MMA(O[4], aph[0], b[0], b[1]);
            MMA(O[5], aph[0], b[2], b[3]);
            LDSM4T(b, Vb + SWZ((brow) * 128 + 96 + bcb));
            MMA(O[6], aph[0], b[0], b[1]);
            MMA(O[7], aph[0], b[2], b[3]);
        }
        #pragma unroll
        for (int kk = 1; kk < 4; kk++) {
            #pragma unroll
            for (int jp = 0; jp < 4; jp++) {
                uint32_t b[4];
                LDSM4T(b, Vb + SWZ((16 * kk + brow) * 128 + 32 * jp + bcb));
                MMA(O[2*jp],   aph[kk], b[0], b[1]);
                MMA(O[2*jp+1], aph[kk], b[2], b[3]);
            }
        }

        // ---- deferred rowsum on fma pipe (aph still live) ----
        #pragma unroll
        for (int kk = 0; kk < 4; kk++) {
            float2 f0 = __half22float2(*reinterpret_cast<__half2*>(&aph[kk][0]));
            float2 f1 = __half22float2(*reinterpret_cast<__half2*>(&aph[kk][1]));
            float2 f2 = __half22float2(*reinterpret_cast<__half2*>(&aph[kk][2]));
            float2 f3 = __half22float2(*reinterpret_cast<__half2*>(&aph[kk][3]));
            lsum0 += (f0.x + f0.y) + (f2.x + f2.y);
            lsum1 += (f1.x + f1.y) + (f3.x + f3.y);
        }

        scur = (scur == 2) ? 0 : scur + 1;
        snxt = (snxt == 2) ? 0 : snxt + 1;
    }

    // ---- finalize: reduce row sums across lane quads, write O / l ----
    lsum0 += __shfl_xor_sync(0xffffffffu, lsum0, 1);
    lsum0 += __shfl_xor_sync(0xffffffffu, lsum0, 2);
    lsum1 += __shfl_xor_sync(0xffffffffu, lsum1, 1);
    lsum1 += __shfl_xor_sync(0xffffffffu, lsum1, 2);
    float inv0 = 1.0f / lsum0;
    float inv1 = 1.0f / lsum1;

    const int row = wrow + (lane >> 2);
    const int cb  = (lane & 3) * 2;
    #pragma unroll
    for (int j = 0; j < 8; j++) {
        float2 o0 = make_float2(O[j][0] * inv0, O[j][1] * inv0);
        float2 o1 = make_float2(O[j][2] * inv1, O[j][3] * inv1);
        *reinterpret_cast<float2*>(ob + (size_t)row * D + 8 * j + cb)       = o0;
        *reinterpret_cast<float2*>(ob + (size_t)(row + 8) * D + 8 * j + cb) = o1;
    }
}

extern "C" void kernel_launch(void* const* d_in, const int* in_sizes, int n_in,
                              void* d_out, int out_size)
{
    const float* q = (const float*)d_in[0];
    const float* k = (const float*)d_in[1];
    const float* v = (const float*)d_in[2];
    float* out = (float*)d_out;
    (void)in_sizes; (void)n_in; (void)out_size;

    // fused prepass: fp32 -> fp16 for K and V
    cvt_kv<<<2 * (NELEM / 8) / 256, 256>>>(k, v);

    cudaFuncSetAttribute(attn_hmma,
                         cudaFuncAttributeMaxDynamicSharedMemorySize, SM_TOTAL);
    dim3 grid(S_LEN / BM, 32);
    attn_hmma<<<grid, 128, SM_TOTAL>>>(q, out);
}

// round 17
// speedup vs baseline: 1.0040x; 1.0040x over previous
#include <cuda_runtime.h>
#include <cuda_fp16.h>
#include <stdint.h>

// SelfAttentionEasy b=2,h=16,s=2048,d=64 fp32
// out = (exp(Q@K/8) @ V) / rowsum(exp(Q@K/8))
// Round 17: QK GEMM with fp16 accumulation (2x HMMA rate), split into two
// d-halves to bound rounding; f16 C-frag == A-frag layout so ex2 consumes
// it directly (no fp32->fp16 cvts). PV stays fp32-accum. R8/R15 shell.

#define S_LEN 2048
#define D     64
#define BM    64
#define BN    64
#define NELEM (2*16*64*2048)          // elements per tensor (k or v)
#define QSCALE 0.18033688011112042f   // log2(e)/8

__device__ __half g_kh[NELEM];        // k as fp16, layout [bh][d][s]
__device__ __half g_vh[NELEM];        // v as fp16, layout [bh][s][d]

#define SM_TOTAL 49152                // 3 stages x (8KB K + 8KB V)

#define SWZ(o) ((uint32_t)(o) ^ ((((uint32_t)(o)) >> 3) & 0x70))

__device__ __forceinline__ uint32_t smem_u32(const void* p) {
    uint32_t a;
    asm("{ .reg .u64 t; cvta.to.shared.u64 t, %1; cvt.u32.u64 %0, t; }"
        : "=r"(a) : "l"(p));
    return a;
}
__device__ __forceinline__ uint32_t h2u(__half2 h) {
    return *reinterpret_cast<uint32_t*>(&h);
}

#define LDSM4(r, a) asm volatile(                                          \
    "ldmatrix.sync.aligned.m8n8.x4.shared.b16 {%0,%1,%2,%3}, [%4];"        \
    : "=r"((r)[0]),"=r"((r)[1]),"=r"((r)[2]),"=r"((r)[3]) : "r"(a))

#define LDSM4T(r, a) asm volatile(                                         \
    "ldmatrix.sync.aligned.m8n8.x4.trans.shared.b16 {%0,%1,%2,%3}, [%4];"  \
    : "=r"((r)[0]),"=r"((r)[1]),"=r"((r)[2]),"=r"((r)[3]) : "r"(a))

// fp32-accum MMA (PV)
#define MMA(c, a, b0, b1) asm volatile(                                    \
    "mma.sync.aligned.m16n8k16.row.col.f32.f16.f16.f32 "                   \
    "{%0,%1,%2,%3},{%4,%5,%6,%7},{%8,%9},{%0,%1,%2,%3};"                   \
    : "+f"((c)[0]),"+f"((c)[1]),"+f"((c)[2]),"+f"((c)[3])                  \
    : "r"((a)[0]),"r"((a)[1]),"r"((a)[2]),"r"((a)[3]),"r"(b0),"r"(b1))

// fp16-accum MMA (QK) — 2x rate; C/D are 2 b32 regs (f16x2 pairs)
#define MMA16(c, a, b0, b1) asm volatile(                                  \
    "mma.sync.aligned.m16n8k16.row.col.f16.f16.f16.f16 "                   \
    "{%0,%1},{%2,%3,%4,%5},{%6,%7},{%0,%1};"                               \
    : "+r"((c)[0]),"+r"((c)[1])                                            \
    : "r"((a)[0]),"r"((a)[1]),"r"((a)[2]),"r"((a)[3]),"r"(b0),"r"(b1))

#define HADD2(d, x, y) asm("add.rn.f16x2 %0, %1, %2;" : "=r"(d) : "r"(x), "r"(y))

#define CPA(dst, src) asm volatile(                                        \
    "cp.async.cg.shared.global [%0], [%1], 16;" :: "r"(dst), "l"(src))
#define CPA_COMMIT() asm volatile("cp.async.commit_group;" ::: "memory")
#define CPA_WAIT1()  asm volatile("cp.async.wait_group 1;" ::: "memory")
#define CPA_WAIT0()  asm volatile("cp.async.wait_group 0;" ::: "memory")

// ---- fused prepass: fp32 -> fp16 bulk convert for K and V ----
__global__ void cvt_kv(const float* __restrict__ k, const float* __restrict__ v) {
    size_t gi = (size_t)blockIdx.x * blockDim.x + threadIdx.x;
    const size_t half = (size_t)NELEM / 8;
    const float* src;
    __half* dst;
    size_t i;
    if (gi < half) { src = k; dst = g_kh; i = gi * 8; }
    else           { src = v; dst = g_vh; i = (gi - half) * 8; }
    float4 a = *reinterpret_cast<const float4*>(src + i);
    float4 b = *reinterpret_cast<const float4*>(src + i + 4);
    uint4 o;
    o.x = h2u(__floats2half2_rn(a.x, a.y));
    o.y = h2u(__floats2half2_rn(a.z, a.w));
    o.z = h2u(__floats2half2_rn(b.x, b.y));
    o.w = h2u(__floats2half2_rn(b.z, b.w));
    *reinterpret_cast<uint4*>(dst + i) = o;
}

__global__ __launch_bounds__(128, 4)
void attn_hmma(const float* __restrict__ q, float* __restrict__ out)
{
    extern __shared__ char smem[];
    const uint32_t sb = smem_u32(smem);
    const int tid = threadIdx.x;
    const int wid = tid >> 5, lane = tid & 31;
    const int bh = blockIdx.y;
    const int q0 = blockIdx.x * BM;

    const float*  qb  = q + (size_t)bh * S_LEN * D + (size_t)q0 * D;
    const __half* khb = g_kh + (size_t)bh * D * S_LEN;
    const __half* vhb = g_vh + (size_t)bh * S_LEN * D;
    float*        ob  = out + (size_t)bh * S_LEN * D + (size_t)q0 * D;

    const int wrow = wid * 16;
    const uint32_t arow = (uint32_t)(wrow + (lane & 15));
    const uint32_t acb  = (uint32_t)(lane & 16);
    const uint32_t brow = (uint32_t)(lane & 15);
    const uint32_t bcb  = (uint32_t)(lane & 16);

    // ---- stage Q once (pre-scaled by log2e/8), hoist frags to regs ----
    #pragma unroll
    for (int i = 0; i < 8; i++) {
        int s = tid + i * 128;                 // 1024 float4 slots
        int row = s >> 4, c4 = s & 15;
        float4 f = *reinterpret_cast<const float4*>(qb + row * D + c4 * 4);
        uint32_t off = SWZ(row * 128 + c4 * 8);
        *reinterpret_cast<uint2*>(smem + off) =
            make_uint2(h2u(__floats2half2_rn(f.x * QSCALE, f.y * QSCALE)),
                       h2u(__floats2half2_rn(f.z * QSCALE, f.w * QSCALE)));
    }
    __syncthreads();
    uint32_t aq[4][4];
    #pragma unroll
    for (int kk = 0; kk < 4; kk++)
        LDSM4(aq[kk], sb + SWZ(arow * 128 + 32 * kk + acb));
    __syncthreads();   // Q frags read; smem reusable

    // per-thread cp.async source rows/chunks (512 K-chunks + 512 V-chunks)
    const int r0_ = (tid      ) >> 3, c0_ = (tid      ) & 7;
    const int r1_ = (tid + 128) >> 3, c1_ = (tid + 128) & 7;
    const int r2_ = (tid + 256) >> 3, c2_ = (tid + 256) & 7;
    const int r3_ = (tid + 384) >> 3, c3_ = (tid + 384) & 7;

    // ---- cp.async prologue: stages for tiles 0 and 1 ----
    #pragma unroll
    for (int p = 0; p < 2; p++) {
        uint32_t kd = sb + p * 16384;
        uint32_t vd = kd + 8192;
        const int t0 = p * BN;
        CPA(kd + SWZ(r0_ * 128 + c0_ * 16), khb + (size_t)r0_ * S_LEN + t0 + c0_ * 8);
        CPA(kd + SWZ(r1_ * 128 + c1_ * 16), khb + (size_t)r1_ * S_LEN + t0 + c1_ * 8);
        CPA(kd + SWZ(r2_ * 128 + c2_ * 16), khb + (size_t)r2_ * S_LEN + t0 + c2_ * 8);
        CPA(kd + SWZ(r3_ * 128 + c3_ * 16), khb + (size_t)r3_ * S_LEN + t0 + c3_ * 8);
        CPA(vd + SWZ(r0_ * 128 + c0_ * 16), vhb + (size_t)(t0 + r0_) * D + c0_ * 8);
        CPA(vd + SWZ(r1_ * 128 + c1_ * 16), vhb + (size_t)(t0 + r1_) * D + c1_ * 8);
        CPA(vd + SWZ(r2_ * 128 + c2_ * 16), vhb + (size_t)(t0 + r2_) * D + c2_ * 8);
        CPA(vd + SWZ(r3_ * 128 + c3_ * 16), vhb + (size_t)(t0 + r3_) * D + c3_ * 8);
        CPA_COMMIT();
    }

    float O[8][4];
    #pragma unroll
    for (int j = 0; j < 8; j++)
        #pragma unroll
        for (int e = 0; e < 4; e++) O[j][e] = 0.f;
    float lsum0 = 0.f, lsum1 = 0.f;

    int scur = 0, snxt = 2;

    for (int t = 0; t < 32; t++) {
        if (t < 31) { CPA_WAIT1(); } else { CPA_WAIT0(); }
        __syncthreads();

        // issue tile t+2 into stage snxt
        if (t + 2 < 32) {
            uint32_t kd = sb + snxt * 16384;
            uint32_t vd = kd + 8192;
            const int t0 = (t + 2) * BN;
            CPA(kd + SWZ(r0_ * 128 + c0_ * 16), khb + (size_t)r0_ * S_LEN + t0 + c0_ * 8);
            CPA(kd + SWZ(r1_ * 128 + c1_ * 16), khb + (size_t)r1_ * S_LEN + t0 + c1_ * 8);
            CPA(kd + SWZ(r2_ * 128 + c2_ * 16), khb + (size_t)r2_ * S_LEN + t0 + c2_ * 8);
            CPA(kd + SWZ(r3_ * 128 + c3_ * 16), khb + (size_t)r3_ * S_LEN + t0 + c3_ * 8);
            CPA(vd + SWZ(r0_ * 128 + c0_ * 16), vhb + (size_t)(t0 + r0_) * D + c0_ * 8);
            CPA(vd + SWZ(r1_ * 128 + c1_ * 16), vhb + (size_t)(t0 + r1_) * D + c1_ * 8);
            CPA(vd + SWZ(r2_ * 128 + c2_ * 16), vhb + (size_t)(t0 + r2_) * D + c2_ * 8);
            CPA(vd + SWZ(r3_ * 128 + c3_ * 16), vhb + (size_t)(t0 + r3_) * D + c3_ * 8);
            CPA_COMMIT();
        }

        const uint32_t Kb = sb + scur * 16384;
        const uint32_t Vb = Kb + 8192;

        // ---- QK in fp16 accumulation, two d-halves (kk 0-1 / 2-3) ----
        uint32_t SA[8][2], SB[8][2];
        #pragma unroll
        for (int j = 0; j < 8; j++) {
            SA[j][0] = SA[j][1] = 0u;
            SB[j][0] = SB[j][1] = 0u;
        }

        #pragma unroll
        for (int kk = 0; kk < 2; kk++) {
            #pragma unroll
            for (int jp = 0; jp < 4; jp++) {
                uint32_t b[4];
                LDSM4T(b, Kb + SWZ((16 * kk + brow) * 128 + 32 * jp + bcb));
                MMA16(SA[2*jp],   aq[kk], b[0], b[1]);
                MMA16(SA[2*jp+1], aq[kk], b[2], b[3]);
            }
        }
        #pragma unroll
        for (int kk = 2; kk < 4; kk++) {
            #pragma unroll
            for (int jp = 0; jp < 4; jp++) {
                uint32_t b[4];
                LDSM4T(b, Kb + SWZ((16 * kk + brow) * 128 + 32 * jp + bcb));
                MMA16(SB[2*jp],   aq[kk], b[0], b[1]);
                MMA16(SB[2*jp+1], aq[kk], b[2], b[3]);
            }
        }

        // ---- prefetch V(jp=0) frags under the ex2 chain ----
        uint32_t vb0[4], vb1[4];
        LDSM4T(vb0, Vb + SWZ((brow) * 128 +  0 + bcb));
        LDSM4T(vb1, Vb + SWZ((brow) * 128 + 32 + bcb));

        // ---- combine halves (HADD2) -> ex2 -> PV A-frags directly ----
        uint32_t aph[4][4];
        #pragma unroll
        for (int j = 0; j < 8; j++) {
            uint32_t u0, u1;
            HADD2(u0, SA[j][0], SB[j][0]);
            HADD2(u1, SA[j][1], SB[j][1]);
            asm("ex2.approx.f16x2 %0, %0;" : "+r"(u0));
            asm("ex2.approx.f16x2 %0, %0;" : "+r"(u1));
            int kk = j >> 1, pc = (j & 1) * 2;
            aph[kk][pc]   = u0;
            aph[kk][pc+1] = u1;
        }

        // ---- O += P @ V (fp32 accum; jp=0 uses prefetched frags) ----
        MMA(O[0], aph[0], vb0[0], vb0[1]);
        MMA(O[1], aph[0], vb0[2], vb0[3]);
        MMA(O[2], aph[0], vb1[0], vb1[1]);
        MMA(O[3], aph[0], vb1[2], vb1[3]);
        {
            uint32_t b[4];
            LDSM4T(b, Vb + SWZ((brow) * 128 + 64 + bcb));
            MMA(O[4], aph[0], b[0], b[1]);
            MMA(O[5], aph[0], b[2], b[3]);
            LDSM4T(b, Vb + SWZ((brow) * 128 + 96 + bcb));
            MMA(O[6], aph[0], b[0], b[1]);
            MMA(O[7], aph[0], b[2], b[3]);
        }
        #pragma unroll
        for (int kk = 1; kk < 4; kk++) {
            #pragma unroll
            for (int jp = 0; jp < 4; jp++) {
                uint32_t b[4];
                LDSM4T(b, Vb + SWZ((16 * kk + brow) * 128 + 32 * jp + bcb));
                MMA(O[2*jp],   aph[kk], b[0], b[1]);
                MMA(O[2*jp+1], aph[kk], b[2], b[3]);
            }
        }

        // ---- deferred rowsum on fma pipe (aph still live) ----
        #pragma unroll
        for (int kk = 0; kk < 4; kk++) {
            float2 f0 = __half22float2(*reinterpret_cast<__half2*>(&aph[kk][0]));
            float2 f1 = __half22float2(*reinterpret_cast<__half2*>(&aph[kk][1]));
            float2 f2 = __half22float2(*reinterpret_cast<__half2*>(&aph[kk][2]));
            float2 f3 = __half22float2(*reinterpret_cast<__half2*>(&aph[kk][3]));
            lsum0 += (f0.x + f0.y) + (f2.x + f2.y);
            lsum1 += (f1.x + f1.y) + (f3.x + f3.y);
        }

        scur = (scur == 2) ? 0 : scur + 1;
        snxt = (snxt == 2) ? 0 : snxt + 1;
    }

    // ---- finalize: reduce row sums across lane quads, write O / l ----
    lsum0 += __shfl_xor_sync(0xffffffffu, lsum0, 1);
    lsum0 += __shfl_xor_sync(0xffffffffu, lsum0, 2);
    lsum1 += __shfl_xor_sync(0xffffffffu, lsum1, 1);
    lsum1 += __shfl_xor_sync(0xffffffffu, lsum1, 2);
    float inv0 = 1.0f / lsum0;
    float inv1 = 1.0f / lsum1;

    const int row = wrow + (lane >> 2);
    const int cb  = (lane & 3) * 2;
    #pragma unroll
    for (int j = 0; j < 8; j++) {
        float2 o0 = make_float2(O[j][0] * inv0, O[j][1] * inv0);
        float2 o1 = make_float2(O[j][2] * inv1, O[j][3] * inv1);
        *reinterpret_cast<float2*>(ob + (size_t)row * D + 8 * j + cb)       = o0;
        *reinterpret_cast<float2*>(ob + (size_t)(row + 8) * D + 8 * j + cb) = o1;
    }
}

extern "C" void kernel_launch(void* const* d_in, const int* in_sizes, int n_in,
                              void* d_out, int out_size)
{
    const float* q = (const float*)d_in[0];
    const float* k = (const float*)d_in[1];
    const float* v = (const float*)d_in[2];
    float* out = (float*)d_out;
    (void)in_sizes; (void)n_in; (void)out_size;

    // fused prepass: fp32 -> fp16 for K and V
    cvt_kv<<<2 * (NELEM / 8) / 256, 256>>>(k, v);

    cudaFuncSetAttribute(attn_hmma,
                         cudaFuncAttributeMaxDynamicSharedMemorySize, SM_TOTAL);
    dim3 grid(S_LEN / BM, 32);
    attn_hmma<<<grid, 128, SM_TOTAL>>>(q, out);
}